// round 3
// baseline (speedup 1.0000x reference)
#include <cuda_runtime.h>

// Problem constants
#define NB   16      // batch
#define NC   64      // channels
#define NH   48      // H == W
#define ND   3072    // xLSTM feature dim (C*W)
#define ND4  12288   // 4*D
#define NT   48      // sequence length
#define NROWS 768    // B*T

// ---------------- device scratch (no allocations allowed) ----------------
__device__ float d_pre1[NROWS * ND4];   // 37.75 MB
__device__ float d_pre2[NROWS * ND4];   // 37.75 MB
__device__ float d_g[NB * ND4];
__device__ float d_cst[NB * ND];
__device__ float d_nst[NB * ND];
__device__ float d_mst[NB * ND];
__device__ float d_hT[ND * NB];         // transposed hidden state [d][b]
__device__ float d_Y1[NROWS * ND];      // hidden outputs stack 1
__device__ float d_Y2[NROWS * ND];      // hidden outputs stack 2
__device__ float d_xh[NB * NC * NH];
__device__ float d_xw[NB * NC * NH];
__device__ float d_sh[NB * NC * NH];
__device__ float d_sw[NB * NC * NH];

// ---------------- packed fp32x2 helpers (Blackwell FFMA2) ----------------
__device__ __forceinline__ unsigned long long pack2(float x, float y) {
    unsigned long long r;
    asm("mov.b64 %0, {%1, %2};" : "=l"(r) : "f"(x), "f"(y));
    return r;
}
__device__ __forceinline__ void fma2(unsigned long long& c, unsigned long long a,
                                     unsigned long long b) {
    asm("fma.rn.f32x2 %0, %1, %2, %0;" : "+l"(c) : "l"(a), "l"(b));
}
__device__ __forceinline__ float2 unpack2(unsigned long long v) {
    float2 f;
    asm("mov.b64 {%0, %1}, %2;" : "=f"(f.x), "=f"(f.y) : "l"(v));
    return f;
}

// ---------------- pre-projection GEMM: pre = X @ W + bias ----------------
// A: [768, 3072] (x viewed flat), W: [3072, 12288], out: [768, 12288]
// 128x128 tile, BK=8, 256 threads, 8x8 microtile via FFMA2.
__global__ void __launch_bounds__(256) sgemm_pre(const float* __restrict__ A,
                                                 const float* __restrict__ Wm,
                                                 const float* __restrict__ bias,
                                                 int which) {
    __shared__ float As[8][128];
    __shared__ float Bs[8][128];
    float* Cout = which ? d_pre2 : d_pre1;

    int tid = threadIdx.x;
    int bm = blockIdx.y, bn = blockIdx.x;
    int arow = tid >> 1, acol = (tid & 1) << 2;
    int brow = tid >> 5, bcol = (tid & 31) << 2;
    int ty = tid >> 4, tx = tid & 15;

    unsigned long long acc[8][4];
#pragma unroll
    for (int i = 0; i < 8; i++)
#pragma unroll
        for (int j = 0; j < 4; j++) acc[i][j] = 0ull;

    const float* Ap = A + (bm * 128 + arow) * ND + acol;
    const float* Bp = Wm + brow * ND4 + bn * 128 + bcol;

    for (int k0 = 0; k0 < ND; k0 += 8) {
        float4 av = *(const float4*)(Ap + k0);
        float4 bv = *(const float4*)(Bp + (size_t)k0 * ND4);
        As[acol + 0][arow] = av.x;
        As[acol + 1][arow] = av.y;
        As[acol + 2][arow] = av.z;
        As[acol + 3][arow] = av.w;
        *(float4*)&Bs[brow][bcol] = bv;
        __syncthreads();
#pragma unroll
        for (int kk = 0; kk < 8; kk++) {
            float4 a0 = *(const float4*)&As[kk][ty * 8];
            float4 a1 = *(const float4*)&As[kk][ty * 8 + 4];
            ulonglong2 bq0 = *(const ulonglong2*)&Bs[kk][tx * 8];
            ulonglong2 bq1 = *(const ulonglong2*)&Bs[kk][tx * 8 + 4];
            unsigned long long rb[4] = {bq0.x, bq0.y, bq1.x, bq1.y};
            float aa[8] = {a0.x, a0.y, a0.z, a0.w, a1.x, a1.y, a1.z, a1.w};
#pragma unroll
            for (int i = 0; i < 8; i++) {
                unsigned long long ra = pack2(aa[i], aa[i]);
#pragma unroll
                for (int j = 0; j < 4; j++) fma2(acc[i][j], ra, rb[j]);
            }
        }
        __syncthreads();
    }

    int cbase = bn * 128 + tx * 8;
    float4 bb0 = *(const float4*)(bias + cbase);
    float4 bb1 = *(const float4*)(bias + cbase + 4);
#pragma unroll
    for (int i = 0; i < 8; i++) {
        int row = bm * 128 + ty * 8 + i;
        float2 v0 = unpack2(acc[i][0]);
        float2 v1 = unpack2(acc[i][1]);
        float2 v2 = unpack2(acc[i][2]);
        float2 v3 = unpack2(acc[i][3]);
        float4 o0 = make_float4(v0.x + bb0.x, v0.y + bb0.y, v1.x + bb0.z, v1.y + bb0.w);
        float4 o1 = make_float4(v2.x + bb1.x, v2.y + bb1.y, v3.x + bb1.z, v3.y + bb1.w);
        *(float4*)(Cout + (size_t)row * ND4 + cbase) = o0;
        *(float4*)(Cout + (size_t)row * ND4 + cbase + 4) = o1;
    }
}

// ---------------- recurrent step GEMM: g = pre[:,t,:] + h @ R ----------------
// grid = 384 blocks (32 cols each), 256 threads = 8 k-slices x 32 cols.
// hT is [3072][16] so slices stage coalesced; inner loop:
// 1 coalesced R LDG + 4 broadcast LDS.128 + 8 FFMA2 per k.
__global__ void __launch_bounds__(256) step_gemm(const float* __restrict__ R,
                                                 int which, int t) {
    __shared__ float smem[8192];  // 32 KB: h-chunk stage, reused for reduction
    const float* pre = which ? d_pre2 : d_pre1;
    int tid = threadIdx.x;
    int ksl = tid >> 5;
    int coll = tid & 31;
    int colg = blockIdx.x * 32 + coll;

    unsigned long long acc[8];
#pragma unroll
    for (int j = 0; j < 8; j++) acc[j] = 0ull;

    const float4* hT4 = (const float4*)d_hT;

    for (int c0 = 0; c0 < 384; c0 += 64) {
        // stage hT chunk: layout [ksl][kk(64)][b(16)]
#pragma unroll
        for (int i = 0; i < 8; i++) {
            int s4 = tid + i * 256;
            int ksl_l = s4 >> 8;
            int rem = s4 & 255;
            ((float4*)smem)[s4] = hT4[ksl_l * 1536 + c0 * 4 + rem];
        }
        __syncthreads();

        const float* rp = R + (ksl * 384 + c0) * ND4 + colg;
#pragma unroll 8
        for (int kk = 0; kk < 64; kk++) {
            float rv = rp[kk * ND4];
            unsigned long long rr = pack2(rv, rv);
            const ulonglong2* hp = (const ulonglong2*)(smem + ((ksl * 64 + kk) << 4));
            ulonglong2 h0 = hp[0], h1 = hp[1];
            fma2(acc[0], rr, h0.x);
            fma2(acc[1], rr, h0.y);
            fma2(acc[2], rr, h1.x);
            fma2(acc[3], rr, h1.y);
            ulonglong2 h2 = hp[2], h3 = hp[3];
            fma2(acc[4], rr, h2.x);
            fma2(acc[5], rr, h2.y);
            fma2(acc[6], rr, h3.x);
            fma2(acc[7], rr, h3.y);
        }
        __syncthreads();
    }

    // cross-slice reduction
    unsigned long long* sa = (unsigned long long*)smem;
#pragma unroll
    for (int j = 0; j < 8; j++) sa[tid * 8 + j] = acc[j];
    __syncthreads();

    if (tid < 32) {
        int cg2 = blockIdx.x * 32 + tid;
#pragma unroll
        for (int j = 0; j < 8; j++) {
            float sx = 0.f, sy = 0.f;
#pragma unroll
            for (int s = 0; s < 8; s++) {
                float2 v = unpack2(sa[((s * 32 + tid) << 3) + j]);
                sx += v.x;
                sy += v.y;
            }
            int b0 = 2 * j, b1 = 2 * j + 1;
            d_g[b0 * ND4 + cg2] = pre[(b0 * NT + t) * ND4 + cg2] + sx;
            d_g[b1 * ND4 + cg2] = pre[(b1 * NT + t) * ND4 + cg2] + sy;
        }
    }
}

// ---------------- sLSTM gate update (elementwise) ----------------
__global__ void gate_step(int which, int t) {
    int idx = blockIdx.x * 256 + threadIdx.x;  // 49152 threads
    int b = idx / ND;
    int d = idx - b * ND;
    float it = d_g[b * ND4 + d];
    float ft = d_g[b * ND4 + ND + d];
    float zt = d_g[b * ND4 + 2 * ND + d];
    float ot = d_g[b * ND4 + 3 * ND + d];
    float m = d_mst[idx];
    float mn = fmaxf(ft + m, it);
    float ig = expf(it - mn);
    float fg = expf(ft + m - mn);
    float cn = fg * d_cst[idx] + ig * tanhf(zt);
    float nn = fg * d_nst[idx] + ig;
    float h = cn / (nn + 1e-6f) * (1.0f / (1.0f + expf(-ot)));
    d_cst[idx] = cn;
    d_nst[idx] = nn;
    d_mst[idx] = mn;
    d_hT[d * NB + b] = h;
    float* Y = which ? d_Y2 : d_Y1;
    Y[b * (NT * ND) + t * ND + d] = h;
}

__global__ void init_state() {
    int idx = blockIdx.x * 256 + threadIdx.x;
    d_cst[idx] = 0.f;
    d_nst[idx] = 0.f;
    d_mst[idx] = 0.f;
    d_hT[idx] = 0.f;
}

// ---------------- spatial means ----------------
// xh[b,c,p] = mean_q Y2[(b*64+c)*2304 + p*48 + q]   (contiguous)
// xw[b,c,p] = mean_q Y1[(b*64+c)*2304 + q*48 + p]   (strided)
__global__ void reduce_means() {
    int bc = blockIdx.x;  // 0..1023 = b*64+c
    int p = threadIdx.x;  // 0..47
    const float* base2 = d_Y2 + bc * 2304;
    const float* base1 = d_Y1 + bc * 2304;
    float s = 0.f;
#pragma unroll 8
    for (int q = 0; q < 48; q++) s += base2[p * 48 + q];
    d_xh[bc * 48 + p] = s * (1.0f / 48.0f);
    float s2 = 0.f;
#pragma unroll 8
    for (int q = 0; q < 48; q++) s2 += base1[q * 48 + p];
    d_xw[bc * 48 + p] = s2 * (1.0f / 48.0f);
}

// ---------------- grouped conv1d + GroupNorm + sigmoid ----------------
// conv: groups=8 (8 in/8 out channels per group), K=5, same padding.
// GN: 16 groups of 4 channels, stats over 4*48 elements.
// block = (b, gn_group): 192 threads = 4 out-channels x 48 positions.
__global__ void conv_gn(const float* __restrict__ cw, const float* __restrict__ gamma,
                        const float* __restrict__ beta) {
    int z = blockIdx.y;
    const float* u = z ? d_xw : d_xh;
    float* o = z ? d_sw : d_sh;
    int bidx = blockIdx.x;
    int b = bidx >> 4, g = bidx & 15;
    __shared__ float uin[8][52];
    __shared__ float wsh[4][8][5];
    __shared__ float svals[192];
    __shared__ float stats[2];
    int tid = threadIdx.x;
    int cg = g >> 1;  // conv group of this GN group's channels

    for (int i = tid; i < 384; i += 192) {
        int ci = i / 48, p = i - ci * 48;
        uin[ci][p + 2] = u[(b * NC + cg * 8 + ci) * 48 + p];
    }
    if (tid < 8) {
        uin[tid][0] = 0.f;
        uin[tid][1] = 0.f;
        uin[tid][50] = 0.f;
        uin[tid][51] = 0.f;
    }
    for (int i = tid; i < 160; i += 192) {
        ((float*)wsh)[i] = cw[g * 160 + i];  // co = 4g..4g+3 rows are contiguous
    }
    __syncthreads();

    int lc = tid / 48, p = tid - lc * 48;
    float v = 0.f;
#pragma unroll
    for (int ci = 0; ci < 8; ci++)
#pragma unroll
        for (int k = 0; k < 5; k++) v += uin[ci][p + k] * wsh[lc][ci][k];

    svals[tid] = v;
    __syncthreads();
    if (tid < 32) {
        float s = 0.f, s2 = 0.f;
#pragma unroll
        for (int i = 0; i < 6; i++) {
            float x = svals[tid + i * 32];
            s += x;
            s2 += x * x;
        }
#pragma unroll
        for (int off = 16; off; off >>= 1) {
            s += __shfl_xor_sync(0xffffffff, s, off);
            s2 += __shfl_xor_sync(0xffffffff, s2, off);
        }
        if (tid == 0) {
            stats[0] = s * (1.0f / 192.0f);
            stats[1] = s2 * (1.0f / 192.0f);
        }
    }
    __syncthreads();
    float mu = stats[0];
    float var = stats[1] - mu * mu;
    int co = 4 * g + lc;
    float xn = (v - mu) * rsqrtf(var + 1e-5f);
    float yv = xn * gamma[co] + beta[co];
    o[(b * NC + co) * 48 + p] = 1.0f / (1.0f + expf(-yv));
}

// ---------------- final: out[b,c,h,w] = sh[b,c,h]*sw[b,c,w]*x ----------------
__global__ void final_mul(const float* __restrict__ x, float* __restrict__ out) {
    int idx = blockIdx.x * 256 + threadIdx.x;  // 2359296 total, exact
    int b = idx / (NC * NH * NH);
    int r = idx - b * (NC * NH * NH);
    int c = r / (NH * NH);
    int r2 = r - c * (NH * NH);
    int h = r2 / NH;
    int w = r2 - h * NH;
    out[idx] = d_sh[(b * NC + c) * 48 + h] * d_sw[(b * NC + c) * 48 + w] * x[idx];
}

// ---------------- launch ----------------
extern "C" void kernel_launch(void* const* d_in, const int* in_sizes, int n_in,
                              void* d_out, int out_size) {
    const float* x  = (const float*)d_in[0];
    const float* W1 = (const float*)d_in[1];
    const float* R1 = (const float*)d_in[2];
    const float* b1 = (const float*)d_in[3];
    const float* W2 = (const float*)d_in[4];
    const float* R2 = (const float*)d_in[5];
    const float* b2 = (const float*)d_in[6];
    const float* cw = (const float*)d_in[7];
    const float* gg = (const float*)d_in[8];
    const float* gb = (const float*)d_in[9];
    float* out = (float*)d_out;

    dim3 gpre(96, 6);
    sgemm_pre<<<gpre, 256>>>(x, W1, b1, 0);
    sgemm_pre<<<gpre, 256>>>(x, W2, b2, 1);

    for (int which = 0; which < 2; which++) {
        init_state<<<192, 256>>>();
        const float* R = which ? R2 : R1;
        for (int t = 0; t < NT; t++) {
            step_gemm<<<384, 256>>>(R, which, t);
            gate_step<<<192, 256>>>(which, t);
        }
    }

    reduce_means<<<1024, 48>>>();
    conv_gn<<<dim3(256, 2), 192>>>(cw, gg, gb);
    final_mul<<<9216, 256>>>(x, out);
}